// round 1
// baseline (speedup 1.0000x reference)
#include <cuda_runtime.h>
#include <math.h>

// Problem constants
#define Bb 2
#define Tt 2048
#define Cc 1024
#define Hh 16
#define Dd 64
#define Ff 4096
#define MM (Bb*Tt)          // 4096 rows
#define ATTN_SCALE 0.125f   // 1/sqrt(64)

// ---------------------------------------------------------------------------
// Scratch (device globals: no allocation allowed in kernel_launch)
// ---------------------------------------------------------------------------
__device__ float d_h  [MM*Cc];   // ln1 output
__device__ float d_q  [MM*Cc];
__device__ float d_k  [MM*Cc];
__device__ float d_v  [MM*Cc];
__device__ float d_ctx[MM*Cc];
__device__ float d_x2 [MM*Cc];   // x + attn out
__device__ float d_h2 [MM*Cc];   // ln2 output
__device__ float d_g  [MM*Ff];   // gelu(h2@W1+b1)

// ---------------------------------------------------------------------------
// LayerNorm: one block per row (C=1024), 256 threads, float4
// ---------------------------------------------------------------------------
__global__ __launch_bounds__(256)
void ln_kernel(const float* __restrict__ x, const float* __restrict__ sc,
               const float* __restrict__ sh, float* __restrict__ out)
{
    int row = blockIdx.x;
    int t   = threadIdx.x;
    const float* xr = x + (size_t)row * Cc;
    float4 v = *(const float4*)(xr + t * 4);

    float s  = v.x + v.y + v.z + v.w;
    float s2 = v.x*v.x + v.y*v.y + v.z*v.z + v.w*v.w;

    #pragma unroll
    for (int off = 16; off; off >>= 1) {
        s  += __shfl_down_sync(0xffffffffu, s,  off);
        s2 += __shfl_down_sync(0xffffffffu, s2, off);
    }
    __shared__ float rs[8], rs2[8];
    __shared__ float mean_s, rstd_s;
    int w = t >> 5, lane = t & 31;
    if (lane == 0) { rs[w] = s; rs2[w] = s2; }
    __syncthreads();
    if (t == 0) {
        float ts = 0.f, ts2 = 0.f;
        #pragma unroll
        for (int i = 0; i < 8; i++) { ts += rs[i]; ts2 += rs2[i]; }
        float mean = ts * (1.0f / Cc);
        float var  = ts2 * (1.0f / Cc) - mean * mean;
        mean_s = mean;
        rstd_s = rsqrtf(var + 1e-5f);
    }
    __syncthreads();
    float mean = mean_s, rstd = rstd_s;

    float4 g  = *(const float4*)(sc + t * 4);
    float4 bb = *(const float4*)(sh + t * 4);
    float4 o;
    o.x = g.x * (v.x - mean) * rstd + bb.x;
    o.y = g.y * (v.y - mean) * rstd + bb.y;
    o.z = g.z * (v.z - mean) * rstd + bb.z;
    o.w = g.w * (v.w - mean) * rstd + bb.w;
    *(float4*)(out + (size_t)row * Cc + t * 4) = o;
}

// ---------------------------------------------------------------------------
// Tiled SGEMM: C[M,N] = A[M,K] @ W[K,N] + bias (+ epilogue)
// Block tile 128x128, K-tile 16, 256 threads, 8x8 per-thread microtile.
// EPI: 0 = bias, 1 = bias + exact GELU, 2 = bias + residual add
// M,N,K all multiples of 128 here -> no bounds checks.
// ---------------------------------------------------------------------------
template<int EPI>
__global__ __launch_bounds__(256)
void gemm_kernel(const float* __restrict__ A, const float* __restrict__ W,
                 const float* __restrict__ bias, const float* __restrict__ res,
                 float* __restrict__ C, int M, int N, int K)
{
    __shared__ float As[16][128];
    __shared__ float Bs[16][128];

    const int tid = threadIdx.x;
    const int m0 = blockIdx.y * 128;
    const int n0 = blockIdx.x * 128;
    const int ty = tid >> 4;      // 0..15
    const int tx = tid & 15;      // 0..15

    float acc[8][8];
    #pragma unroll
    for (int r = 0; r < 8; r++)
        #pragma unroll
        for (int c = 0; c < 8; c++) acc[r][c] = 0.f;

    for (int k0 = 0; k0 < K; k0 += 16) {
        // Load A tile [128 x 16], store transposed As[k][m]
        #pragma unroll
        for (int i = 0; i < 2; i++) {
            int l   = tid + i * 256;       // 0..511
            int row = l >> 2;              // 0..127
            int c4  = l & 3;               // 0..3
            float4 a4 = *(const float4*)(A + (size_t)(m0 + row) * K + k0 + c4 * 4);
            As[c4*4+0][row] = a4.x;
            As[c4*4+1][row] = a4.y;
            As[c4*4+2][row] = a4.z;
            As[c4*4+3][row] = a4.w;
        }
        // Load B tile [16 x 128]
        #pragma unroll
        for (int i = 0; i < 2; i++) {
            int l   = tid + i * 256;
            int row = l >> 5;              // 0..15
            int c4  = l & 31;              // 0..31
            *(float4*)&Bs[row][c4 * 4] =
                *(const float4*)(W + (size_t)(k0 + row) * N + n0 + c4 * 4);
        }
        __syncthreads();

        #pragma unroll
        for (int kk = 0; kk < 16; kk++) {
            float a[8], b[8];
            *(float4*)&a[0] = *(float4*)&As[kk][ty * 8 + 0];
            *(float4*)&a[4] = *(float4*)&As[kk][ty * 8 + 4];
            *(float4*)&b[0] = *(float4*)&Bs[kk][tx * 8 + 0];
            *(float4*)&b[4] = *(float4*)&Bs[kk][tx * 8 + 4];
            #pragma unroll
            for (int r = 0; r < 8; r++)
                #pragma unroll
                for (int c = 0; c < 8; c++)
                    acc[r][c] += a[r] * b[c];
        }
        __syncthreads();
    }

    // Epilogue
    float bv[8];
    *(float4*)&bv[0] = *(const float4*)(bias + n0 + tx * 8 + 0);
    *(float4*)&bv[4] = *(const float4*)(bias + n0 + tx * 8 + 4);

    #pragma unroll
    for (int r = 0; r < 8; r++) {
        int row = m0 + ty * 8 + r;
        float o[8];
        #pragma unroll
        for (int c = 0; c < 8; c++) {
            float v = acc[r][c] + bv[c];
            if (EPI == 1) v = 0.5f * v * (1.0f + erff(v * 0.70710678118654752f));
            o[c] = v;
        }
        if (EPI == 2) {
            float4 r0 = *(const float4*)(res + (size_t)row * N + n0 + tx * 8 + 0);
            float4 r1 = *(const float4*)(res + (size_t)row * N + n0 + tx * 8 + 4);
            o[0] += r0.x; o[1] += r0.y; o[2] += r0.z; o[3] += r0.w;
            o[4] += r1.x; o[5] += r1.y; o[6] += r1.z; o[7] += r1.w;
        }
        *(float4*)(C + (size_t)row * N + n0 + tx * 8 + 0) = make_float4(o[0], o[1], o[2], o[3]);
        *(float4*)(C + (size_t)row * N + n0 + tx * 8 + 4) = make_float4(o[4], o[5], o[6], o[7]);
    }
}

// ---------------------------------------------------------------------------
// Causal flash attention.
// Q,K,V layout: [B, T, H, D] contiguous (row stride H*D = 1024 floats).
// Grid: (T/128, H, B). 128 threads; thread owns one q row (q + acc in regs).
// K/V tiles of 32 rows staged in smem; online softmax.
// ---------------------------------------------------------------------------
__global__ __launch_bounds__(128)
void attn_kernel(const float* __restrict__ Q, const float* __restrict__ K,
                 const float* __restrict__ V, float* __restrict__ O)
{
    const int b  = blockIdx.z;
    const int h  = blockIdx.y;
    const int qt = blockIdx.x;
    const int tid = threadIdx.x;
    const int qi = qt * 128 + tid;          // global q row (always < T)

    __shared__ float ks[32][68];            // pad 68: rows 16B-aligned
    __shared__ float vs[32][68];

    // Load q row into registers, pre-scaled by 1/sqrt(D)
    const float* qp = Q + ((size_t)(b * Tt + qi) * Hh + h) * Dd;
    float q[Dd], acc[Dd];
    #pragma unroll
    for (int d = 0; d < Dd; d += 4) {
        float4 t4 = *(const float4*)(qp + d);
        q[d+0] = t4.x * ATTN_SCALE;
        q[d+1] = t4.y * ATTN_SCALE;
        q[d+2] = t4.z * ATTN_SCALE;
        q[d+3] = t4.w * ATTN_SCALE;
        acc[d+0] = 0.f; acc[d+1] = 0.f; acc[d+2] = 0.f; acc[d+3] = 0.f;
    }

    float m = -1e30f, l = 0.f;
    const int ntiles = qt * 4 + 4;          // tiles of 32 keys covering k <= qt*128+127

    for (int kt = 0; kt < ntiles; kt++) {
        __syncthreads();
        // Cooperative load of K/V tile: 32 rows x 64 cols = 512 float4, 4 per thread
        const float* kbase = K + ((size_t)(b * Tt + kt * 32) * Hh + h) * Dd;
        const float* vbase = V + ((size_t)(b * Tt + kt * 32) * Hh + h) * Dd;
        #pragma unroll
        for (int i = 0; i < 4; i++) {
            int idx = tid + i * 128;        // 0..511
            int j   = idx >> 4;             // 0..31  (row)
            int d4  = idx & 15;             // 0..15  (float4 within row)
            *(float4*)&ks[j][d4 * 4] = *(const float4*)(kbase + (size_t)j * (Hh * Dd) + d4 * 4);
            *(float4*)&vs[j][d4 * 4] = *(const float4*)(vbase + (size_t)j * (Hh * Dd) + d4 * 4);
        }
        __syncthreads();

        // Scores for 32 keys
        float s[32];
        #pragma unroll
        for (int j = 0; j < 32; j++) {
            float sum = 0.f;
            #pragma unroll
            for (int d = 0; d < Dd; d += 4) {
                float4 k4 = *(const float4*)&ks[j][d];
                sum += q[d+0]*k4.x + q[d+1]*k4.y + q[d+2]*k4.z + q[d+3]*k4.w;
            }
            int kg = kt * 32 + j;
            s[j] = (kg <= qi) ? sum : -1e30f;
        }

        // Online softmax update
        float mt = m;
        #pragma unroll
        for (int j = 0; j < 32; j++) mt = fmaxf(mt, s[j]);
        float fac = __expf(m - mt);
        m = mt;
        l *= fac;
        #pragma unroll
        for (int d = 0; d < Dd; d++) acc[d] *= fac;

        #pragma unroll
        for (int j = 0; j < 32; j++) {
            float p = __expf(s[j] - m);
            l += p;
            #pragma unroll
            for (int d = 0; d < Dd; d += 4) {
                float4 v4 = *(const float4*)&vs[j][d];
                acc[d+0] += p * v4.x;
                acc[d+1] += p * v4.y;
                acc[d+2] += p * v4.z;
                acc[d+3] += p * v4.w;
            }
        }
    }

    float inv = 1.0f / l;
    float* op = O + ((size_t)(b * Tt + qi) * Hh + h) * Dd;
    #pragma unroll
    for (int d = 0; d < Dd; d += 4) {
        *(float4*)(op + d) = make_float4(acc[d+0]*inv, acc[d+1]*inv, acc[d+2]*inv, acc[d+3]*inv);
    }
}

// ---------------------------------------------------------------------------
// Launch
// ---------------------------------------------------------------------------
extern "C" void kernel_launch(void* const* d_in, const int* in_sizes, int n_in,
                              void* d_out, int out_size)
{
    const float* x   = (const float*)d_in[0];
    const float* Wq  = (const float*)d_in[1];
    const float* bq  = (const float*)d_in[2];
    const float* Wk  = (const float*)d_in[3];
    const float* bk  = (const float*)d_in[4];
    const float* Wv  = (const float*)d_in[5];
    const float* bv  = (const float*)d_in[6];
    const float* Wo  = (const float*)d_in[7];
    const float* bo  = (const float*)d_in[8];
    const float* W1  = (const float*)d_in[9];
    const float* b1  = (const float*)d_in[10];
    const float* W2  = (const float*)d_in[11];
    const float* b2  = (const float*)d_in[12];
    const float* ln1s = (const float*)d_in[13];
    const float* ln1b = (const float*)d_in[14];
    const float* ln2s = (const float*)d_in[15];
    const float* ln2b = (const float*)d_in[16];
    float* out = (float*)d_out;

    float *h, *q, *k, *v, *ctx, *x2, *h2, *g;
    cudaGetSymbolAddress((void**)&h,   d_h);
    cudaGetSymbolAddress((void**)&q,   d_q);
    cudaGetSymbolAddress((void**)&k,   d_k);
    cudaGetSymbolAddress((void**)&v,   d_v);
    cudaGetSymbolAddress((void**)&ctx, d_ctx);
    cudaGetSymbolAddress((void**)&x2,  d_x2);
    cudaGetSymbolAddress((void**)&h2,  d_h2);
    cudaGetSymbolAddress((void**)&g,   d_g);

    dim3 gemm_tb(256);
    dim3 grid_c(Cc / 128, MM / 128);   // N=1024
    dim3 grid_f(Ff / 128, MM / 128);   // N=4096

    // 1. h = LN1(x)
    ln_kernel<<<MM, 256>>>(x, ln1s, ln1b, h);
    // 2. q,k,v = h@W{q,k,v} + b
    gemm_kernel<0><<<grid_c, gemm_tb>>>(h, Wq, bq, nullptr, q, MM, Cc, Cc);
    gemm_kernel<0><<<grid_c, gemm_tb>>>(h, Wk, bk, nullptr, k, MM, Cc, Cc);
    gemm_kernel<0><<<grid_c, gemm_tb>>>(h, Wv, bv, nullptr, v, MM, Cc, Cc);
    // 3. ctx = causal_softmax(q k^T / sqrt(D)) v
    attn_kernel<<<dim3(Tt / 128, Hh, Bb), 128>>>(q, k, v, ctx);
    // 4. x2 = x + ctx@Wo + bo
    gemm_kernel<2><<<grid_c, gemm_tb>>>(ctx, Wo, bo, x, x2, MM, Cc, Cc);
    // 5. h2 = LN2(x2)
    ln_kernel<<<MM, 256>>>(x2, ln2s, ln2b, h2);
    // 6. g = gelu(h2@W1 + b1)
    gemm_kernel<1><<<grid_f, gemm_tb>>>(h2, W1, b1, nullptr, g, MM, Ff, Cc);
    // 7. out = x2 + g@W2 + b2
    gemm_kernel<2><<<grid_c, gemm_tb>>>(g, W2, b2, x2, out, MM, Cc, Ff);
}

// round 3
// speedup vs baseline: 1.9174x; 1.9174x over previous
#include <cuda_runtime.h>
#include <cuda_bf16.h>
#include <math.h>
#include <stdint.h>

#define Bb 2
#define Tt 2048
#define Cc 1024
#define Hh 16
#define Dd 64
#define Ff 4096
#define MM (Bb*Tt)
#define ATTN_SCALE 0.125f

// ---------------------------------------------------------------------------
// Scratch (device globals)
// ---------------------------------------------------------------------------
__device__ float d_q [MM*Cc];
__device__ float d_k [MM*Cc];
__device__ float d_v [MM*Cc];
__device__ float d_x2[MM*Cc];

__device__ __nv_bfloat16 d_hh [MM*Cc], d_hl [MM*Cc];
__device__ __nv_bfloat16 d_ch [MM*Cc], d_cl [MM*Cc];    // ctx
__device__ __nv_bfloat16 d_h2h[MM*Cc], d_h2l[MM*Cc];
__device__ __nv_bfloat16 d_gh [MM*Ff], d_gl [MM*Ff];

// transposed+split weights: layout [N][K], K contiguous
__device__ __nv_bfloat16 d_wqh[Cc*Cc], d_wql[Cc*Cc];
__device__ __nv_bfloat16 d_wkh[Cc*Cc], d_wkl[Cc*Cc];
__device__ __nv_bfloat16 d_wvh[Cc*Cc], d_wvl[Cc*Cc];
__device__ __nv_bfloat16 d_woh[Cc*Cc], d_wol[Cc*Cc];
__device__ __nv_bfloat16 d_w1h[Ff*Cc], d_w1l[Ff*Cc];
__device__ __nv_bfloat16 d_w2h[Cc*Ff], d_w2l[Cc*Ff];

// ---------------------------------------------------------------------------
// Helpers
// ---------------------------------------------------------------------------
__device__ __forceinline__ uint32_t smem_u32(const void* p) {
    uint32_t a;
    asm("{ .reg .u64 t; cvta.to.shared.u64 t, %1; cvt.u32.u64 %0, t; }" : "=r"(a) : "l"(p));
    return a;
}

#define CP16(dst, src) asm volatile("cp.async.cg.shared.global [%0], [%1], 16;" :: "r"(dst), "l"(src) : "memory")
#define CP_COMMIT()    asm volatile("cp.async.commit_group;" ::: "memory")
#define CP_WAIT0()     asm volatile("cp.async.wait_group 0;" ::: "memory")
#define CP_WAIT1()     asm volatile("cp.async.wait_group 1;" ::: "memory")

#define LDMX4(r0,r1,r2,r3,addr) \
    asm volatile("ldmatrix.sync.aligned.m8n8.x4.shared.b16 {%0,%1,%2,%3}, [%4];" \
        : "=r"(r0),"=r"(r1),"=r"(r2),"=r"(r3) : "r"(addr))

#define MMA16816(c, a, b0v, b1v) \
    asm volatile("mma.sync.aligned.m16n8k16.row.col.f32.bf16.bf16.f32 " \
        "{%0,%1,%2,%3}, {%4,%5,%6,%7}, {%8,%9}, {%0,%1,%2,%3};" \
        : "+f"((c)[0]),"+f"((c)[1]),"+f"((c)[2]),"+f"((c)[3]) \
        : "r"((a)[0]),"r"((a)[1]),"r"((a)[2]),"r"((a)[3]), "r"(b0v),"r"(b1v))

__device__ __forceinline__ uint32_t sw128(uint32_t off) {
    return off ^ ((off >> 3) & 0x70);
}

// ---------------------------------------------------------------------------
// LayerNorm fused -> bf16 hi/lo
// ---------------------------------------------------------------------------
__global__ __launch_bounds__(256)
void ln_bf16_kernel(const float* __restrict__ x, const float* __restrict__ sc,
                    const float* __restrict__ sh,
                    __nv_bfloat16* __restrict__ oh, __nv_bfloat16* __restrict__ ol)
{
    int row = blockIdx.x;
    int t   = threadIdx.x;
    const float* xr = x + (size_t)row * Cc;
    float4 v = *(const float4*)(xr + t * 4);

    float s  = v.x + v.y + v.z + v.w;
    float s2 = v.x*v.x + v.y*v.y + v.z*v.z + v.w*v.w;
    #pragma unroll
    for (int off = 16; off; off >>= 1) {
        s  += __shfl_down_sync(0xffffffffu, s,  off);
        s2 += __shfl_down_sync(0xffffffffu, s2, off);
    }
    __shared__ float rs[8], rs2[8];
    __shared__ float mean_s, rstd_s;
    int w = t >> 5, lane = t & 31;
    if (lane == 0) { rs[w] = s; rs2[w] = s2; }
    __syncthreads();
    if (t == 0) {
        float ts = 0.f, ts2 = 0.f;
        #pragma unroll
        for (int i = 0; i < 8; i++) { ts += rs[i]; ts2 += rs2[i]; }
        float mean = ts * (1.0f / Cc);
        float var  = ts2 * (1.0f / Cc) - mean * mean;
        mean_s = mean;
        rstd_s = rsqrtf(var + 1e-5f);
    }
    __syncthreads();
    float mean = mean_s, rstd = rstd_s;

    float4 g  = *(const float4*)(sc + t * 4);
    float4 bb = *(const float4*)(sh + t * 4);
    float o[4];
    o[0] = g.x * (v.x - mean) * rstd + bb.x;
    o[1] = g.y * (v.y - mean) * rstd + bb.y;
    o[2] = g.z * (v.z - mean) * rstd + bb.z;
    o[3] = g.w * (v.w - mean) * rstd + bb.w;

    __nv_bfloat16 hb[4], lb[4];
    #pragma unroll
    for (int i = 0; i < 4; i++) {
        hb[i] = __float2bfloat16(o[i]);
        lb[i] = __float2bfloat16(o[i] - __bfloat162float(hb[i]));
    }
    size_t base = (size_t)row * Cc + t * 4;
    *(uint2*)(oh + base) = *(uint2*)hb;
    *(uint2*)(ol + base) = *(uint2*)lb;
}

// ---------------------------------------------------------------------------
// Weight transpose + bf16 split: W[K,N] -> Wt_hi/lo[N,K]
// ---------------------------------------------------------------------------
__global__ __launch_bounds__(256)
void wconv_kernel(const float* __restrict__ W,
                  __nv_bfloat16* __restrict__ Wth, __nv_bfloat16* __restrict__ Wtl,
                  int K, int N)
{
    __shared__ float tile[32][33];
    int n0 = blockIdx.x * 32, k0 = blockIdx.y * 32;
    int tx = threadIdx.x, ty = threadIdx.y;   // 32 x 8
    #pragma unroll
    for (int j = 0; j < 4; j++)
        tile[ty + 8*j][tx] = W[(size_t)(k0 + ty + 8*j) * N + n0 + tx];
    __syncthreads();
    #pragma unroll
    for (int j = 0; j < 4; j++) {
        float v = tile[tx][ty + 8*j];
        __nv_bfloat16 hv = __float2bfloat16(v);
        __nv_bfloat16 lv = __float2bfloat16(v - __bfloat162float(hv));
        size_t o = (size_t)(n0 + ty + 8*j) * K + k0 + tx;
        Wth[o] = hv;
        Wtl[o] = lv;
    }
}

// ---------------------------------------------------------------------------
// mma.sync split-bf16 GEMM: C[M,N] = (Ah+Al)[M,K] @ (Wh+Wl)^T[N,K] + bias
// 3 accumulation passes: Ah*Wh, Ah*Wl, Al*Wh -> fp32 register accumulators.
// Block tile 128x128, BK=64; 8 warps in 4(m) x 2(n); warp tile 32x64.
// EPI: 0 = bias -> fp32 ; 1 = bias+GELU -> bf16 hi/lo ; 2 = bias+res -> fp32
// ---------------------------------------------------------------------------
#define SMEM_GEMM (4*16384)

template<int EPI>
__global__ __launch_bounds__(256, 2)
void tcgemm(const __nv_bfloat16* __restrict__ Ah, const __nv_bfloat16* __restrict__ Al,
            const __nv_bfloat16* __restrict__ Bh, const __nv_bfloat16* __restrict__ Bl,
            const float* __restrict__ bias, const float* __restrict__ res,
            float* __restrict__ Cf,
            __nv_bfloat16* __restrict__ Coh, __nv_bfloat16* __restrict__ Col,
            int K, int N)
{
    extern __shared__ char smem[];
    const uint32_t sb = smem_u32(smem);
    const int tid = threadIdx.x;
    const int m0 = blockIdx.y * 128, n0 = blockIdx.x * 128;
    const int KT = K >> 6;
    const int NT = 3 * KT;

    const uint32_t sA[2] = { sb,         sb + 32768 };
    const uint32_t sB[2] = { sb + 16384, sb + 49152 };

    const int lane = tid & 31;
    const int wid  = tid >> 5;
    const int wm   = (wid & 3) * 32;   // warp m offset in tile
    const int wn   = (wid >> 2) * 64;  // warp n offset in tile

    // ldmatrix lane-address components
    const int a_row = wm + (lane & 15);
    const int a_cb  = (lane >> 4) << 4;                       // 0 or 16 bytes
    const int b_row = wn + ((lane >> 4) << 3) + (lane & 7);
    const int b_cb  = ((lane >> 3) & 1) << 4;                 // 0 or 16 bytes

    float acc[2][4][8];
    #pragma unroll
    for (int mg = 0; mg < 2; mg++)
        #pragma unroll
        for (int ng = 0; ng < 4; ng++)
            #pragma unroll
            for (int r = 0; r < 8; r++) acc[mg][ng][r] = 0.f;

    const __nv_bfloat16* Ap[3] = { Ah, Ah, Al };
    const __nv_bfloat16* Bp[3] = { Bh, Bl, Bh };

    auto load_tile = [&](int bsel, int p, int k0e) {
        const __nv_bfloat16* Asrc = Ap[p];
        const __nv_bfloat16* Bsrc = Bp[p];
        #pragma unroll
        for (int j = 0; j < 4; j++) {
            int lin = tid + j * 256;
            int r = lin >> 3, c = lin & 7;
            uint32_t sw = sw128((uint32_t)(r * 128 + c * 16));
            CP16(sA[bsel] + sw, Asrc + (size_t)(m0 + r) * K + k0e + c * 8);
            CP16(sB[bsel] + sw, Bsrc + (size_t)(n0 + r) * K + k0e + c * 8);
        }
        CP_COMMIT();
    };

    load_tile(0, 0, 0);

    for (int i = 0; i < NT; i++) {
        int nx = i + 1;
        if (nx < NT) {
            int p  = (nx >= 2 * KT) ? 2 : ((nx >= KT) ? 1 : 0);
            int kt = nx - p * KT;
            load_tile(nx & 1, p, kt * 64);
            CP_WAIT1();
        } else {
            CP_WAIT0();
        }
        __syncthreads();

        const uint32_t bufA = sA[i & 1];
        const uint32_t bufB = sB[i & 1];
        #pragma unroll
        for (int ks = 0; ks < 4; ks++) {
            uint32_t a[2][4];
            #pragma unroll
            for (int mg = 0; mg < 2; mg++) {
                uint32_t off = (uint32_t)((a_row + mg * 16) * 128 + ks * 32 + a_cb);
                LDMX4(a[mg][0], a[mg][1], a[mg][2], a[mg][3], bufA + sw128(off));
            }
            #pragma unroll
            for (int ng = 0; ng < 4; ng++) {
                uint32_t b0, b1, b2, b3;
                uint32_t off = (uint32_t)((b_row + ng * 16) * 128 + ks * 32 + b_cb);
                LDMX4(b0, b1, b2, b3, bufB + sw128(off));
                #pragma unroll
                for (int mg = 0; mg < 2; mg++) {
                    MMA16816(acc[mg][ng] + 0, a[mg], b0, b1);
                    MMA16816(acc[mg][ng] + 4, a[mg], b2, b3);
                }
            }
        }
        __syncthreads();
    }

    // Epilogue straight from register fragments.
    // c frag: c0,c1 -> row (lane>>2), cols 2*(lane&3)+{0,1}; c2,c3 -> row+8.
    const int rbase = m0 + wm + (lane >> 2);
    const int cb0   = n0 + wn + (lane & 3) * 2;
    #pragma unroll
    for (int mg = 0; mg < 2; mg++) {
        #pragma unroll
        for (int ng = 0; ng < 4; ng++) {
            #pragma unroll
            for (int ns = 0; ns < 2; ns++) {
                const float* c4 = acc[mg][ng] + ns * 4;
                int cc = cb0 + ng * 16 + ns * 8;
                float bx = __ldg(bias + cc), by = __ldg(bias + cc + 1);
                #pragma unroll
                for (int half = 0; half < 2; half++) {
                    int r = rbase + mg * 16 + half * 8;
                    float vx = c4[half * 2 + 0] + bx;
                    float vy = c4[half * 2 + 1] + by;
                    if (EPI == 1) {
                        vx = 0.5f * vx * (1.0f + erff(vx * 0.70710678118654752f));
                        vy = 0.5f * vy * (1.0f + erff(vy * 0.70710678118654752f));
                        __nv_bfloat16 hx = __float2bfloat16(vx);
                        __nv_bfloat16 hy = __float2bfloat16(vy);
                        __nv_bfloat16 lx = __float2bfloat16(vx - __bfloat162float(hx));
                        __nv_bfloat16 ly = __float2bfloat16(vy - __bfloat162float(hy));
                        __nv_bfloat162 hp; hp.x = hx; hp.y = hy;
                        __nv_bfloat162 lp; lp.x = lx; lp.y = ly;
                        *(__nv_bfloat162*)(Coh + (size_t)r * N + cc) = hp;
                        *(__nv_bfloat162*)(Col + (size_t)r * N + cc) = lp;
                    } else {
                        if (EPI == 2) {
                            float2 rr = *(const float2*)(res + (size_t)r * N + cc);
                            vx += rr.x; vy += rr.y;
                        }
                        float2 o; o.x = vx; o.y = vy;
                        *(float2*)(Cf + (size_t)r * N + cc) = o;
                    }
                }
            }
        }
    }
}

// ---------------------------------------------------------------------------
// Causal flash attention (fp32 SIMT), epilogue writes ctx as bf16 hi/lo.
// ---------------------------------------------------------------------------
__global__ __launch_bounds__(128)
void attn_kernel(const float* __restrict__ Q, const float* __restrict__ K,
                 const float* __restrict__ V,
                 __nv_bfloat16* __restrict__ Oh, __nv_bfloat16* __restrict__ Ol)
{
    const int b   = blockIdx.z;
    const int hd  = blockIdx.y;
    const int qt  = blockIdx.x;
    const int tid = threadIdx.x;
    const int qi  = qt * 128 + tid;

    __shared__ float ks[32][68];
    __shared__ float vs[32][68];

    const float* qp = Q + ((size_t)(b * Tt + qi) * Hh + hd) * Dd;
    float q[Dd], acc[Dd];
    #pragma unroll
    for (int d = 0; d < Dd; d += 4) {
        float4 t4 = *(const float4*)(qp + d);
        q[d+0] = t4.x * ATTN_SCALE; q[d+1] = t4.y * ATTN_SCALE;
        q[d+2] = t4.z * ATTN_SCALE; q[d+3] = t4.w * ATTN_SCALE;
        acc[d+0] = 0.f; acc[d+1] = 0.f; acc[d+2] = 0.f; acc[d+3] = 0.f;
    }

    float m = -1e30f, l = 0.f;
    const int ntiles = qt * 4 + 4;

    for (int kt = 0; kt < ntiles; kt++) {
        __syncthreads();
        const float* kbase = K + ((size_t)(b * Tt + kt * 32) * Hh + hd) * Dd;
        const float* vbase = V + ((size_t)(b * Tt + kt * 32) * Hh + hd) * Dd;
        #pragma unroll
        for (int i = 0; i < 4; i++) {
            int idx = tid + i * 128;
            int j = idx >> 4, d4 = idx & 15;
            *(float4*)&ks[j][d4*4] = *(const float4*)(kbase + (size_t)j * (Hh*Dd) + d4*4);
            *(float4*)&vs[j][d4*4] = *(const float4*)(vbase + (size_t)j * (Hh*Dd) + d4*4);
        }
        __syncthreads();

        float s[32];
        #pragma unroll
        for (int j = 0; j < 32; j++) {
            float sum = 0.f;
            #pragma unroll
            for (int d = 0; d < Dd; d += 4) {
                float4 k4 = *(const float4*)&ks[j][d];
                sum += q[d+0]*k4.x + q[d+1]*k4.y + q[d+2]*k4.z + q[d+3]*k4.w;
            }
            int kg = kt * 32 + j;
            s[j] = (kg <= qi) ? sum : -1e30f;
        }

        float mt = m;
        #pragma unroll
        for (int j = 0; j < 32; j++) mt = fmaxf(mt, s[j]);
        float fac = __expf(m - mt);
        m = mt;
        l *= fac;
        #pragma unroll
        for (int d = 0; d < Dd; d++) acc[d] *= fac;

        #pragma unroll
        for (int j = 0; j < 32; j++) {
            float p = __expf(s[j] - m);
            l += p;
            #pragma unroll
            for (int d = 0; d < Dd; d += 4) {
                float4 v4 = *(const float4*)&vs[j][d];
                acc[d+0] += p * v4.x; acc[d+1] += p * v4.y;
                acc[d+2] += p * v4.z; acc[d+3] += p * v4.w;
            }
        }
    }

    float inv = 1.0f / l;
    size_t obase = ((size_t)(b * Tt + qi) * Hh + hd) * Dd;
    #pragma unroll
    for (int d = 0; d < Dd; d += 8) {
        __nv_bfloat16 hb[8], lb[8];
        #pragma unroll
        for (int e = 0; e < 8; e++) {
            float o = acc[d + e] * inv;
            hb[e] = __float2bfloat16(o);
            lb[e] = __float2bfloat16(o - __bfloat162float(hb[e]));
        }
        *(uint4*)(Oh + obase + d) = *(uint4*)hb;
        *(uint4*)(Ol + obase + d) = *(uint4*)lb;
    }
}

// ---------------------------------------------------------------------------
// Launch
// ---------------------------------------------------------------------------
extern "C" void kernel_launch(void* const* d_in, const int* in_sizes, int n_in,
                              void* d_out, int out_size)
{
    const float* x    = (const float*)d_in[0];
    const float* Wq   = (const float*)d_in[1];
    const float* bq   = (const float*)d_in[2];
    const float* Wk   = (const float*)d_in[3];
    const float* bk   = (const float*)d_in[4];
    const float* Wv   = (const float*)d_in[5];
    const float* bv   = (const float*)d_in[6];
    const float* Wo   = (const float*)d_in[7];
    const float* bo   = (const float*)d_in[8];
    const float* W1   = (const float*)d_in[9];
    const float* b1   = (const float*)d_in[10];
    const float* W2   = (const float*)d_in[11];
    const float* b2   = (const float*)d_in[12];
    const float* ln1s = (const float*)d_in[13];
    const float* ln1b = (const float*)d_in[14];
    const float* ln2s = (const float*)d_in[15];
    const float* ln2b = (const float*)d_in[16];
    float* out = (float*)d_out;

    float *q, *k, *v, *x2;
    cudaGetSymbolAddress((void**)&q,  d_q);
    cudaGetSymbolAddress((void**)&k,  d_k);
    cudaGetSymbolAddress((void**)&v,  d_v);
    cudaGetSymbolAddress((void**)&x2, d_x2);

    __nv_bfloat16 *hh,*hl,*ch,*cl,*h2h,*h2l,*gh,*gl;
    __nv_bfloat16 *wqh,*wql,*wkh,*wkl,*wvh,*wvl,*woh,*wol,*w1h,*w1l,*w2h,*w2l;
    cudaGetSymbolAddress((void**)&hh,  d_hh);   cudaGetSymbolAddress((void**)&hl,  d_hl);
    cudaGetSymbolAddress((void**)&ch,  d_ch);   cudaGetSymbolAddress((void**)&cl,  d_cl);
    cudaGetSymbolAddress((void**)&h2h, d_h2h);  cudaGetSymbolAddress((void**)&h2l, d_h2l);
    cudaGetSymbolAddress((void**)&gh,  d_gh);   cudaGetSymbolAddress((void**)&gl,  d_gl);
    cudaGetSymbolAddress((void**)&wqh, d_wqh);  cudaGetSymbolAddress((void**)&wql, d_wql);
    cudaGetSymbolAddress((void**)&wkh, d_wkh);  cudaGetSymbolAddress((void**)&wkl, d_wkl);
    cudaGetSymbolAddress((void**)&wvh, d_wvh);  cudaGetSymbolAddress((void**)&wvl, d_wvl);
    cudaGetSymbolAddress((void**)&woh, d_woh);  cudaGetSymbolAddress((void**)&wol, d_wol);
    cudaGetSymbolAddress((void**)&w1h, d_w1h);  cudaGetSymbolAddress((void**)&w1l, d_w1l);
    cudaGetSymbolAddress((void**)&w2h, d_w2h);  cudaGetSymbolAddress((void**)&w2l, d_w2l);

    cudaFuncSetAttribute(tcgemm<0>, cudaFuncAttributeMaxDynamicSharedMemorySize, SMEM_GEMM);
    cudaFuncSetAttribute(tcgemm<1>, cudaFuncAttributeMaxDynamicSharedMemorySize, SMEM_GEMM);
    cudaFuncSetAttribute(tcgemm<2>, cudaFuncAttributeMaxDynamicSharedMemorySize, SMEM_GEMM);

    dim3 wblk(32, 8);
    wconv_kernel<<<dim3(Cc/32, Cc/32), wblk>>>(Wq, wqh, wql, Cc, Cc);
    wconv_kernel<<<dim3(Cc/32, Cc/32), wblk>>>(Wk, wkh, wkl, Cc, Cc);
    wconv_kernel<<<dim3(Cc/32, Cc/32), wblk>>>(Wv, wvh, wvl, Cc, Cc);
    wconv_kernel<<<dim3(Cc/32, Cc/32), wblk>>>(Wo, woh, wol, Cc, Cc);
    wconv_kernel<<<dim3(Ff/32, Cc/32), wblk>>>(W1, w1h, w1l, Cc, Ff);
    wconv_kernel<<<dim3(Cc/32, Ff/32), wblk>>>(W2, w2h, w2l, Ff, Cc);

    dim3 grid_c(Cc/128, MM/128);   // (8, 32)
    dim3 grid_f(Ff/128, MM/128);   // (32, 32)

    // 1. h = LN1(x)  -> bf16 hi/lo
    ln_bf16_kernel<<<MM, 256>>>(x, ln1s, ln1b, hh, hl);
    // 2. q,k,v
    tcgemm<0><<<grid_c, 256, SMEM_GEMM>>>(hh, hl, wqh, wql, bq, nullptr, q, nullptr, nullptr, Cc, Cc);
    tcgemm<0><<<grid_c, 256, SMEM_GEMM>>>(hh, hl, wkh, wkl, bk, nullptr, k, nullptr, nullptr, Cc, Cc);
    tcgemm<0><<<grid_c, 256, SMEM_GEMM>>>(hh, hl, wvh, wvl, bv, nullptr, v, nullptr, nullptr, Cc, Cc);
    // 3. attention -> ctx bf16 hi/lo
    attn_kernel<<<dim3(Tt/128, Hh, Bb), 128>>>(q, k, v, ch, cl);
    // 4. x2 = x + ctx@Wo + bo
    tcgemm<2><<<grid_c, 256, SMEM_GEMM>>>(ch, cl, woh, wol, bo, x, x2, nullptr, nullptr, Cc, Cc);
    // 5. h2 = LN2(x2)
    ln_bf16_kernel<<<MM, 256>>>(x2, ln2s, ln2b, h2h, h2l);
    // 6. g = gelu(h2@W1 + b1) -> bf16 hi/lo
    tcgemm<1><<<grid_f, 256, SMEM_GEMM>>>(h2h, h2l, w1h, w1l, b1, nullptr, nullptr, gh, gl, Cc, Ff);
    // 7. out = x2 + g@W2 + b2
    tcgemm<2><<<grid_c, 256, SMEM_GEMM>>>(gh, gl, w2h, w2l, b2, x2, out, nullptr, nullptr, Ff, Cc);
}

// round 4
// speedup vs baseline: 3.4251x; 1.7863x over previous
#include <cuda_runtime.h>
#include <cuda_bf16.h>
#include <math.h>
#include <stdint.h>

#define Bb 2
#define Tt 2048
#define Cc 1024
#define Hh 16
#define Dd 64
#define Ff 4096
#define MM (Bb*Tt)

// ---------------------------------------------------------------------------
// Scratch (device globals)
// ---------------------------------------------------------------------------
__device__ float d_x2[MM*Cc];

__device__ __nv_bfloat16 d_hh [MM*Cc], d_hl [MM*Cc];
__device__ __nv_bfloat16 d_ch [MM*Cc], d_cl [MM*Cc];    // ctx
__device__ __nv_bfloat16 d_h2h[MM*Cc], d_h2l[MM*Cc];
__device__ __nv_bfloat16 d_gh [MM*Ff], d_gl [MM*Ff];

// Q/K/V in [B,H,T,D] bf16 hi/lo
__device__ __nv_bfloat16 d_qbh[Bb*Hh*Tt*Dd], d_qbl[Bb*Hh*Tt*Dd];
__device__ __nv_bfloat16 d_kbh[Bb*Hh*Tt*Dd], d_kbl[Bb*Hh*Tt*Dd];
__device__ __nv_bfloat16 d_vbh[Bb*Hh*Tt*Dd], d_vbl[Bb*Hh*Tt*Dd];

// transposed+split weights: layout [N][K], K contiguous
__device__ __nv_bfloat16 d_wqh[Cc*Cc], d_wql[Cc*Cc];
__device__ __nv_bfloat16 d_wkh[Cc*Cc], d_wkl[Cc*Cc];
__device__ __nv_bfloat16 d_wvh[Cc*Cc], d_wvl[Cc*Cc];
__device__ __nv_bfloat16 d_woh[Cc*Cc], d_wol[Cc*Cc];
__device__ __nv_bfloat16 d_w1h[Ff*Cc], d_w1l[Ff*Cc];
__device__ __nv_bfloat16 d_w2h[Cc*Ff], d_w2l[Cc*Ff];

// ---------------------------------------------------------------------------
// Helpers
// ---------------------------------------------------------------------------
__device__ __forceinline__ uint32_t smem_u32(const void* p) {
    uint32_t a;
    asm("{ .reg .u64 t; cvta.to.shared.u64 t, %1; cvt.u32.u64 %0, t; }" : "=r"(a) : "l"(p));
    return a;
}

#define CP16(dst, src) asm volatile("cp.async.cg.shared.global [%0], [%1], 16;" :: "r"(dst), "l"(src) : "memory")
#define CP_COMMIT()    asm volatile("cp.async.commit_group;" ::: "memory")
#define CP_WAIT0()     asm volatile("cp.async.wait_group 0;" ::: "memory")
#define CP_WAIT1()     asm volatile("cp.async.wait_group 1;" ::: "memory")

#define LDMX4(r0,r1,r2,r3,addr) \
    asm volatile("ldmatrix.sync.aligned.m8n8.x4.shared.b16 {%0,%1,%2,%3}, [%4];" \
        : "=r"(r0),"=r"(r1),"=r"(r2),"=r"(r3) : "r"(addr))

#define LDMT4(r0,r1,r2,r3,addr) \
    asm volatile("ldmatrix.sync.aligned.m8n8.x4.trans.shared.b16 {%0,%1,%2,%3}, [%4];" \
        : "=r"(r0),"=r"(r1),"=r"(r2),"=r"(r3) : "r"(addr))

#define MMA16816(c, a, b0v, b1v) \
    asm volatile("mma.sync.aligned.m16n8k16.row.col.f32.bf16.bf16.f32 " \
        "{%0,%1,%2,%3}, {%4,%5,%6,%7}, {%8,%9}, {%0,%1,%2,%3};" \
        : "+f"((c)[0]),"+f"((c)[1]),"+f"((c)[2]),"+f"((c)[3]) \
        : "r"((a)[0]),"r"((a)[1]),"r"((a)[2]),"r"((a)[3]), "r"(b0v),"r"(b1v))

__device__ __forceinline__ uint32_t sw128(uint32_t off) {
    return off ^ ((off >> 3) & 0x70);
}

// split two fp32 into bf16-hi pair and bf16-lo pair (packed b32 words)
__device__ __forceinline__ void split2(float x0, float x1, uint32_t& hw, uint32_t& lw) {
    __nv_bfloat16 h0 = __float2bfloat16(x0), h1 = __float2bfloat16(x1);
    __nv_bfloat16 l0 = __float2bfloat16(x0 - __bfloat162float(h0));
    __nv_bfloat16 l1 = __float2bfloat16(x1 - __bfloat162float(h1));
    __nv_bfloat162 hp; hp.x = h0; hp.y = h1;
    __nv_bfloat162 lp; lp.x = l0; lp.y = l1;
    hw = *(uint32_t*)&hp;
    lw = *(uint32_t*)&lp;
}

// ---------------------------------------------------------------------------
// LayerNorm fused -> bf16 hi/lo
// ---------------------------------------------------------------------------
__global__ __launch_bounds__(256)
void ln_bf16_kernel(const float* __restrict__ x, const float* __restrict__ sc,
                    const float* __restrict__ sh,
                    __nv_bfloat16* __restrict__ oh, __nv_bfloat16* __restrict__ ol)
{
    int row = blockIdx.x;
    int t   = threadIdx.x;
    const float* xr = x + (size_t)row * Cc;
    float4 v = *(const float4*)(xr + t * 4);

    float s  = v.x + v.y + v.z + v.w;
    float s2 = v.x*v.x + v.y*v.y + v.z*v.z + v.w*v.w;
    #pragma unroll
    for (int off = 16; off; off >>= 1) {
        s  += __shfl_down_sync(0xffffffffu, s,  off);
        s2 += __shfl_down_sync(0xffffffffu, s2, off);
    }
    __shared__ float rs[8], rs2[8];
    __shared__ float mean_s, rstd_s;
    int w = t >> 5, lane = t & 31;
    if (lane == 0) { rs[w] = s; rs2[w] = s2; }
    __syncthreads();
    if (t == 0) {
        float ts = 0.f, ts2 = 0.f;
        #pragma unroll
        for (int i = 0; i < 8; i++) { ts += rs[i]; ts2 += rs2[i]; }
        float mean = ts * (1.0f / Cc);
        float var  = ts2 * (1.0f / Cc) - mean * mean;
        mean_s = mean;
        rstd_s = rsqrtf(var + 1e-5f);
    }
    __syncthreads();
    float mean = mean_s, rstd = rstd_s;

    float4 g  = *(const float4*)(sc + t * 4);
    float4 bb = *(const float4*)(sh + t * 4);
    float o[4];
    o[0] = g.x * (v.x - mean) * rstd + bb.x;
    o[1] = g.y * (v.y - mean) * rstd + bb.y;
    o[2] = g.z * (v.z - mean) * rstd + bb.z;
    o[3] = g.w * (v.w - mean) * rstd + bb.w;

    __nv_bfloat16 hb[4], lb[4];
    #pragma unroll
    for (int i = 0; i < 4; i++) {
        hb[i] = __float2bfloat16(o[i]);
        lb[i] = __float2bfloat16(o[i] - __bfloat162float(hb[i]));
    }
    size_t base = (size_t)row * Cc + t * 4;
    *(uint2*)(oh + base) = *(uint2*)hb;
    *(uint2*)(ol + base) = *(uint2*)lb;
}

// ---------------------------------------------------------------------------
// Weight transpose + bf16 split: W[K,N] -> Wt_hi/lo[N,K]
// ---------------------------------------------------------------------------
__global__ __launch_bounds__(256)
void wconv_kernel(const float* __restrict__ W,
                  __nv_bfloat16* __restrict__ Wth, __nv_bfloat16* __restrict__ Wtl,
                  int K, int N)
{
    __shared__ float tile[32][33];
    int n0 = blockIdx.x * 32, k0 = blockIdx.y * 32;
    int tx = threadIdx.x, ty = threadIdx.y;   // 32 x 8
    #pragma unroll
    for (int j = 0; j < 4; j++)
        tile[ty + 8*j][tx] = W[(size_t)(k0 + ty + 8*j) * N + n0 + tx];
    __syncthreads();
    #pragma unroll
    for (int j = 0; j < 4; j++) {
        float v = tile[tx][ty + 8*j];
        __nv_bfloat16 hv = __float2bfloat16(v);
        __nv_bfloat16 lv = __float2bfloat16(v - __bfloat162float(hv));
        size_t o = (size_t)(n0 + ty + 8*j) * K + k0 + tx;
        Wth[o] = hv;
        Wtl[o] = lv;
    }
}

// ---------------------------------------------------------------------------
// mma.sync split-bf16 GEMM, 3 accumulation passes (AhWh, AhWl, AlWh).
// EPI: 1 = bias+GELU -> bf16 hi/lo [M,N] ; 2 = bias+res -> fp32 [M,N]
//      3 = (bias+acc)*mult -> bf16 hi/lo in [B,H,T,D] layout (QKV)
// ---------------------------------------------------------------------------
#define SMEM_GEMM (4*16384)

template<int EPI>
__global__ __launch_bounds__(256, 2)
void tcgemm(const __nv_bfloat16* __restrict__ Ah, const __nv_bfloat16* __restrict__ Al,
            const __nv_bfloat16* __restrict__ Bh, const __nv_bfloat16* __restrict__ Bl,
            const float* __restrict__ bias, const float* __restrict__ res,
            float* __restrict__ Cf,
            __nv_bfloat16* __restrict__ Coh, __nv_bfloat16* __restrict__ Col,
            int K, int N, float mult)
{
    extern __shared__ char smem[];
    const uint32_t sb = smem_u32(smem);
    const int tid = threadIdx.x;
    const int m0 = blockIdx.y * 128, n0 = blockIdx.x * 128;
    const int KT = K >> 6;
    const int NT = 3 * KT;

    const uint32_t sA[2] = { sb,         sb + 32768 };
    const uint32_t sB[2] = { sb + 16384, sb + 49152 };

    const int lane = tid & 31;
    const int wid  = tid >> 5;
    const int wm   = (wid & 3) * 32;
    const int wn   = (wid >> 2) * 64;

    const int a_row = wm + (lane & 15);
    const int a_cb  = (lane >> 4) << 4;
    const int b_row = wn + ((lane >> 4) << 3) + (lane & 7);
    const int b_cb  = ((lane >> 3) & 1) << 4;

    float acc[2][4][8];
    #pragma unroll
    for (int mg = 0; mg < 2; mg++)
        #pragma unroll
        for (int ng = 0; ng < 4; ng++)
            #pragma unroll
            for (int r = 0; r < 8; r++) acc[mg][ng][r] = 0.f;

    const __nv_bfloat16* Ap[3] = { Ah, Ah, Al };
    const __nv_bfloat16* Bp[3] = { Bh, Bl, Bh };

    auto load_tile = [&](int bsel, int p, int k0e) {
        const __nv_bfloat16* Asrc = Ap[p];
        const __nv_bfloat16* Bsrc = Bp[p];
        #pragma unroll
        for (int j = 0; j < 4; j++) {
            int lin = tid + j * 256;
            int r = lin >> 3, c = lin & 7;
            uint32_t sw = sw128((uint32_t)(r * 128 + c * 16));
            CP16(sA[bsel] + sw, Asrc + (size_t)(m0 + r) * K + k0e + c * 8);
            CP16(sB[bsel] + sw, Bsrc + (size_t)(n0 + r) * K + k0e + c * 8);
        }
        CP_COMMIT();
    };

    load_tile(0, 0, 0);

    for (int i = 0; i < NT; i++) {
        int nx = i + 1;
        if (nx < NT) {
            int p  = (nx >= 2 * KT) ? 2 : ((nx >= KT) ? 1 : 0);
            int kt = nx - p * KT;
            load_tile(nx & 1, p, kt * 64);
            CP_WAIT1();
        } else {
            CP_WAIT0();
        }
        __syncthreads();

        const uint32_t bufA = sA[i & 1];
        const uint32_t bufB = sB[i & 1];
        #pragma unroll
        for (int ks = 0; ks < 4; ks++) {
            uint32_t a[2][4];
            #pragma unroll
            for (int mg = 0; mg < 2; mg++) {
                uint32_t off = (uint32_t)((a_row + mg * 16) * 128 + ks * 32 + a_cb);
                LDMX4(a[mg][0], a[mg][1], a[mg][2], a[mg][3], bufA + sw128(off));
            }
            #pragma unroll
            for (int ng = 0; ng < 4; ng++) {
                uint32_t b0, b1, b2, b3;
                uint32_t off = (uint32_t)((b_row + ng * 16) * 128 + ks * 32 + b_cb);
                LDMX4(b0, b1, b2, b3, bufB + sw128(off));
                #pragma unroll
                for (int mg = 0; mg < 2; mg++) {
                    MMA16816(acc[mg][ng] + 0, a[mg], b0, b1);
                    MMA16816(acc[mg][ng] + 4, a[mg], b2, b3);
                }
            }
        }
        __syncthreads();
    }

    const int rbase = m0 + wm + (lane >> 2);
    const int cb0   = n0 + wn + (lane & 3) * 2;
    #pragma unroll
    for (int mg = 0; mg < 2; mg++) {
        #pragma unroll
        for (int ng = 0; ng < 4; ng++) {
            #pragma unroll
            for (int ns = 0; ns < 2; ns++) {
                const float* c4 = acc[mg][ng] + ns * 4;
                int cc = cb0 + ng * 16 + ns * 8;
                float bx = __ldg(bias + cc), by = __ldg(bias + cc + 1);
                #pragma unroll
                for (int half = 0; half < 2; half++) {
                    int r = rbase + mg * 16 + half * 8;
                    float vx = c4[half * 2 + 0] + bx;
                    float vy = c4[half * 2 + 1] + by;
                    if (EPI == 1) {
                        vx = 0.5f * vx * (1.0f + erff(vx * 0.70710678118654752f));
                        vy = 0.5f * vy * (1.0f + erff(vy * 0.70710678118654752f));
                        uint32_t hw, lw;
                        split2(vx, vy, hw, lw);
                        size_t ob = (size_t)r * N + cc;
                        *(uint32_t*)(Coh + ob) = hw;
                        *(uint32_t*)(Col + ob) = lw;
                    } else if (EPI == 3) {
                        vx *= mult; vy *= mult;
                        uint32_t hw, lw;
                        split2(vx, vy, hw, lw);
                        int bidx = r >> 11, t = r & 2047;
                        int hidx = cc >> 6, dd = cc & 63;
                        size_t idx = (((size_t)(bidx * Hh + hidx) * Tt + t) * Dd + dd);
                        *(uint32_t*)(Coh + idx) = hw;
                        *(uint32_t*)(Col + idx) = lw;
                    } else {
                        if (EPI == 2) {
                            float2 rr = *(const float2*)(res + (size_t)r * N + cc);
                            vx += rr.x; vy += rr.y;
                        }
                        float2 o; o.x = vx; o.y = vy;
                        *(float2*)(Cf + (size_t)r * N + cc) = o;
                    }
                }
            }
        }
    }
}

// ---------------------------------------------------------------------------
// Causal flash attention on mma.sync, split-bf16 for scores and PV.
// Grid: (T/128, H, B), 256 threads. Warp w owns q-rows [w*16, w*16+16).
// K/V tiles of 64 keys; smem stage = {Kh,Kl,Vh,Vl} 8KB each, double buffered.
// Output: ctx bf16 hi/lo in [token][H*D] layout.
// ---------------------------------------------------------------------------
#define SMEM_ATTN 65536

__global__ __launch_bounds__(256)
void attn_mma(const __nv_bfloat16* __restrict__ Qh, const __nv_bfloat16* __restrict__ Ql,
              const __nv_bfloat16* __restrict__ Kh, const __nv_bfloat16* __restrict__ Kl,
              const __nv_bfloat16* __restrict__ Vh, const __nv_bfloat16* __restrict__ Vl,
              __nv_bfloat16* __restrict__ Oh, __nv_bfloat16* __restrict__ Ol)
{
    extern __shared__ char smem[];
    const uint32_t sb = smem_u32(smem);
    const int tid  = threadIdx.x;
    const int lane = tid & 31;
    const int wid  = tid >> 5;
    const int qt   = (gridDim.x - 1) - blockIdx.x;   // largest tiles first
    const int hd   = blockIdx.y, bz = blockIdx.z;
    const size_t hb = ((size_t)(bz * Hh + hd)) * Tt * Dd;
    const int wm   = wid * 16;

    // ---- Load Q tile (128x64 h+l) into stage0 region, extract to registers
    {
        #pragma unroll
        for (int jj = 0; jj < 8; jj++) {
            const __nv_bfloat16* src = (jj < 4) ? Qh : Ql;
            int within = (jj & 3) * 256 + tid;
            int r = within >> 3, c = within & 7;
            CP16(sb + (jj >> 2) * 16384 + sw128((uint32_t)(r * 128 + c * 16)),
                 src + hb + (size_t)(qt * 128 + r) * Dd + c * 8);
        }
        CP_COMMIT(); CP_WAIT0();
    }
    __syncthreads();

    uint32_t qfh[4][4], qfl[4][4];
    {
        int qrow = wm + (lane & 15);
        int qcb  = (lane >> 4) << 4;
        #pragma unroll
        for (int ks = 0; ks < 4; ks++) {
            uint32_t off = (uint32_t)(qrow * 128 + ks * 32 + qcb);
            LDMX4(qfh[ks][0], qfh[ks][1], qfh[ks][2], qfh[ks][3], sb + sw128(off));
            LDMX4(qfl[ks][0], qfl[ks][1], qfl[ks][2], qfl[ks][3], sb + 16384 + sw128(off));
        }
    }
    __syncthreads();

    float acc[8][4];
    #pragma unroll
    for (int nt = 0; nt < 8; nt++)
        #pragma unroll
        for (int e = 0; e < 4; e++) acc[nt][e] = 0.f;
    float mrow0 = -1e30f, mrow1 = -1e30f, lrow0 = 0.f, lrow1 = 0.f;

    const int brow = ((lane >> 4) << 3) + (lane & 7);
    const int bcb  = ((lane >> 3) & 1) << 4;
    const int vrow = (((lane >> 3) & 1) << 3) + (lane & 7);
    const int vcb  = (lane >> 4) << 4;

    auto load_kv = [&](int st, int j) {
        #pragma unroll
        for (int jj = 0; jj < 8; jj++) {
            const __nv_bfloat16* src = (jj < 2) ? Kh : (jj < 4) ? Kl : (jj < 6) ? Vh : Vl;
            int within = (jj & 1) * 256 + tid;
            int r = within >> 3, c = within & 7;
            CP16(sb + st * 32768 + (jj >> 1) * 8192 + sw128((uint32_t)(r * 128 + c * 16)),
                 src + hb + (size_t)(j * 64 + r) * Dd + c * 8);
        }
        CP_COMMIT();
    };

    const int ntiles = 2 * qt + 2;
    load_kv(0, 0);

    for (int j = 0; j < ntiles; j++) {
        if (j + 1 < ntiles) { load_kv((j + 1) & 1, j + 1); CP_WAIT1(); }
        else CP_WAIT0();
        __syncthreads();
        const uint32_t st = sb + (j & 1) * 32768;

        // ---- scores S = Qh*Kh + Ql*Kh + Qh*Kl
        float s[8][4];
        #pragma unroll
        for (int nt = 0; nt < 8; nt++)
            #pragma unroll
            for (int e = 0; e < 4; e++) s[nt][e] = 0.f;

        #pragma unroll
        for (int ks = 0; ks < 4; ks++) {
            #pragma unroll
            for (int g = 0; g < 4; g++) {
                uint32_t roff = (uint32_t)((g * 16 + brow) * 128 + ks * 32 + bcb);
                uint32_t bh0, bh1, bh2, bh3, bl0, bl1, bl2, bl3;
                LDMX4(bh0, bh1, bh2, bh3, st + sw128(roff));
                LDMX4(bl0, bl1, bl2, bl3, st + 8192 + sw128(roff));
                MMA16816(s[2*g],   qfh[ks], bh0, bh1);
                MMA16816(s[2*g+1], qfh[ks], bh2, bh3);
                MMA16816(s[2*g],   qfl[ks], bh0, bh1);
                MMA16816(s[2*g+1], qfl[ks], bh2, bh3);
                MMA16816(s[2*g],   qfh[ks], bl0, bl1);
                MMA16816(s[2*g+1], qfh[ks], bl2, bl3);
            }
        }

        // ---- causal mask (only last two tiles can touch the diagonal)
        if (j >= 2 * qt) {
            int q0 = qt * 128 + wm + (lane >> 2);
            int kb = j * 64 + (lane & 3) * 2;
            #pragma unroll
            for (int nt = 0; nt < 8; nt++) {
                int kg = kb + nt * 8;
                if (kg     > q0)     s[nt][0] = -1e30f;
                if (kg + 1 > q0)     s[nt][1] = -1e30f;
                if (kg     > q0 + 8) s[nt][2] = -1e30f;
                if (kg + 1 > q0 + 8) s[nt][3] = -1e30f;
            }
        }

        // ---- online softmax
        float mx0 = -1e30f, mx1 = -1e30f;
        #pragma unroll
        for (int nt = 0; nt < 8; nt++) {
            mx0 = fmaxf(mx0, fmaxf(s[nt][0], s[nt][1]));
            mx1 = fmaxf(mx1, fmaxf(s[nt][2], s[nt][3]));
        }
        mx0 = fmaxf(mx0, __shfl_xor_sync(0xffffffffu, mx0, 1));
        mx0 = fmaxf(mx0, __shfl_xor_sync(0xffffffffu, mx0, 2));
        mx1 = fmaxf(mx1, __shfl_xor_sync(0xffffffffu, mx1, 1));
        mx1 = fmaxf(mx1, __shfl_xor_sync(0xffffffffu, mx1, 2));
        float mn0 = fmaxf(mrow0, mx0), mn1 = fmaxf(mrow1, mx1);
        float fac0 = __expf(mrow0 - mn0), fac1 = __expf(mrow1 - mn1);
        mrow0 = mn0; mrow1 = mn1;

        float lad0 = 0.f, lad1 = 0.f;
        #pragma unroll
        for (int nt = 0; nt < 8; nt++) {
            s[nt][0] = __expf(s[nt][0] - mn0);
            s[nt][1] = __expf(s[nt][1] - mn0);
            s[nt][2] = __expf(s[nt][2] - mn1);
            s[nt][3] = __expf(s[nt][3] - mn1);
            lad0 += s[nt][0] + s[nt][1];
            lad1 += s[nt][2] + s[nt][3];
        }
        lrow0 = lrow0 * fac0 + lad0;
        lrow1 = lrow1 * fac1 + lad1;
        #pragma unroll
        for (int nt = 0; nt < 8; nt++) {
            acc[nt][0] *= fac0; acc[nt][1] *= fac0;
            acc[nt][2] *= fac1; acc[nt][3] *= fac1;
        }

        // ---- pack P into A-fragments (hi/lo)
        uint32_t ph[4][4], pl[4][4];
        #pragma unroll
        for (int kk = 0; kk < 4; kk++) {
            split2(s[2*kk][0],   s[2*kk][1],   ph[kk][0], pl[kk][0]);
            split2(s[2*kk][2],   s[2*kk][3],   ph[kk][1], pl[kk][1]);
            split2(s[2*kk+1][0], s[2*kk+1][1], ph[kk][2], pl[kk][2]);
            split2(s[2*kk+1][2], s[2*kk+1][3], ph[kk][3], pl[kk][3]);
        }

        // ---- PV: acc += Ph*Vh + Pl*Vh + Ph*Vl
        #pragma unroll
        for (int kk = 0; kk < 4; kk++) {
            #pragma unroll
            for (int g = 0; g < 4; g++) {
                uint32_t roff = (uint32_t)((kk * 16 + vrow) * 128 + g * 32 + vcb);
                uint32_t v0, v1, v2, v3, w0, w1, w2, w3;
                LDMT4(v0, v1, v2, v3, st + 16384 + sw128(roff));
                LDMT4(w0, w1, w2, w3, st + 24576 + sw128(roff));
                MMA16816(acc[2*g],   ph[kk], v0, v1);
                MMA16816(acc[2*g+1], ph[kk], v2, v3);
                MMA16816(acc[2*g],   pl[kk], v0, v1);
                MMA16816(acc[2*g+1], pl[kk], v2, v3);
                MMA16816(acc[2*g],   ph[kk], w0, w1);
                MMA16816(acc[2*g+1], ph[kk], w2, w3);
            }
        }
        __syncthreads();
    }

    // ---- finalize: l reduce, normalize, write ctx bf16 hi/lo [token][H*D]
    lrow0 += __shfl_xor_sync(0xffffffffu, lrow0, 1);
    lrow0 += __shfl_xor_sync(0xffffffffu, lrow0, 2);
    lrow1 += __shfl_xor_sync(0xffffffffu, lrow1, 1);
    lrow1 += __shfl_xor_sync(0xffffffffu, lrow1, 2);
    float inv0 = 1.0f / lrow0, inv1 = 1.0f / lrow1;

    int tok0 = bz * Tt + qt * 128 + wm + (lane >> 2);
    int colb = hd * 64 + (lane & 3) * 2;
    #pragma unroll
    for (int nt = 0; nt < 8; nt++) {
        uint32_t hw, lw;
        split2(acc[nt][0] * inv0, acc[nt][1] * inv0, hw, lw);
        size_t o0 = (size_t)tok0 * Cc + colb + nt * 8;
        *(uint32_t*)(Oh + o0) = hw;
        *(uint32_t*)(Ol + o0) = lw;
        split2(acc[nt][2] * inv1, acc[nt][3] * inv1, hw, lw);
        size_t o1 = (size_t)(tok0 + 8) * Cc + colb + nt * 8;
        *(uint32_t*)(Oh + o1) = hw;
        *(uint32_t*)(Ol + o1) = lw;
    }
}

// ---------------------------------------------------------------------------
// Launch
// ---------------------------------------------------------------------------
extern "C" void kernel_launch(void* const* d_in, const int* in_sizes, int n_in,
                              void* d_out, int out_size)
{
    const float* x    = (const float*)d_in[0];
    const float* Wq   = (const float*)d_in[1];
    const float* bq   = (const float*)d_in[2];
    const float* Wk   = (const float*)d_in[3];
    const float* bk   = (const float*)d_in[4];
    const float* Wv   = (const float*)d_in[5];
    const float* bv   = (const float*)d_in[6];
    const float* Wo   = (const float*)d_in[7];
    const float* bo   = (const float*)d_in[8];
    const float* W1   = (const float*)d_in[9];
    const float* b1   = (const float*)d_in[10];
    const float* W2   = (const float*)d_in[11];
    const float* b2   = (const float*)d_in[12];
    const float* ln1s = (const float*)d_in[13];
    const float* ln1b = (const float*)d_in[14];
    const float* ln2s = (const float*)d_in[15];
    const float* ln2b = (const float*)d_in[16];
    float* out = (float*)d_out;

    float *x2;
    cudaGetSymbolAddress((void**)&x2, d_x2);

    __nv_bfloat16 *hh,*hl,*ch,*cl,*h2h,*h2l,*gh,*gl;
    __nv_bfloat16 *qbh,*qbl,*kbh,*kbl,*vbh,*vbl;
    __nv_bfloat16 *wqh,*wql,*wkh,*wkl,*wvh,*wvl,*woh,*wol,*w1h,*w1l,*w2h,*w2l;
    cudaGetSymbolAddress((void**)&hh,  d_hh);   cudaGetSymbolAddress((void**)&hl,  d_hl);
    cudaGetSymbolAddress((void**)&ch,  d_ch);   cudaGetSymbolAddress((void**)&cl,  d_cl);
    cudaGetSymbolAddress((void**)&h2h, d_h2h);  cudaGetSymbolAddress((void**)&h2l, d_h2l);
    cudaGetSymbolAddress((void**)&gh,  d_gh);   cudaGetSymbolAddress((void**)&gl,  d_gl);
    cudaGetSymbolAddress((void**)&qbh, d_qbh);  cudaGetSymbolAddress((void**)&qbl, d_qbl);
    cudaGetSymbolAddress((void**)&kbh, d_kbh);  cudaGetSymbolAddress((void**)&kbl, d_kbl);
    cudaGetSymbolAddress((void**)&vbh, d_vbh);  cudaGetSymbolAddress((void**)&vbl, d_vbl);
    cudaGetSymbolAddress((void**)&wqh, d_wqh);  cudaGetSymbolAddress((void**)&wql, d_wql);
    cudaGetSymbolAddress((void**)&wkh, d_wkh);  cudaGetSymbolAddress((void**)&wkl, d_wkl);
    cudaGetSymbolAddress((void**)&wvh, d_wvh);  cudaGetSymbolAddress((void**)&wvl, d_wvl);
    cudaGetSymbolAddress((void**)&woh, d_woh);  cudaGetSymbolAddress((void**)&wol, d_wol);
    cudaGetSymbolAddress((void**)&w1h, d_w1h);  cudaGetSymbolAddress((void**)&w1l, d_w1l);
    cudaGetSymbolAddress((void**)&w2h, d_w2h);  cudaGetSymbolAddress((void**)&w2l, d_w2l);

    cudaFuncSetAttribute(tcgemm<1>, cudaFuncAttributeMaxDynamicSharedMemorySize, SMEM_GEMM);
    cudaFuncSetAttribute(tcgemm<2>, cudaFuncAttributeMaxDynamicSharedMemorySize, SMEM_GEMM);
    cudaFuncSetAttribute(tcgemm<3>, cudaFuncAttributeMaxDynamicSharedMemorySize, SMEM_GEMM);
    cudaFuncSetAttribute(attn_mma,  cudaFuncAttributeMaxDynamicSharedMemorySize, SMEM_ATTN);

    dim3 wblk(32, 8);
    wconv_kernel<<<dim3(Cc/32, Cc/32), wblk>>>(Wq, wqh, wql, Cc, Cc);
    wconv_kernel<<<dim3(Cc/32, Cc/32), wblk>>>(Wk, wkh, wkl, Cc, Cc);
    wconv_kernel<<<dim3(Cc/32, Cc/32), wblk>>>(Wv, wvh, wvl, Cc, Cc);
    wconv_kernel<<<dim3(Cc/32, Cc/32), wblk>>>(Wo, woh, wol, Cc, Cc);
    wconv_kernel<<<dim3(Ff/32, Cc/32), wblk>>>(W1, w1h, w1l, Cc, Ff);
    wconv_kernel<<<dim3(Cc/32, Ff/32), wblk>>>(W2, w2h, w2l, Ff, Cc);

    dim3 grid_c(Cc/128, MM/128);   // (8, 32)
    dim3 grid_f(Ff/128, MM/128);   // (32, 32)

    // 1. h = LN1(x)
    ln_bf16_kernel<<<MM, 256>>>(x, ln1s, ln1b, hh, hl);
    // 2. q,k,v -> bf16 hi/lo [B,H,T,D]; Q pre-scaled by 1/sqrt(D)
    tcgemm<3><<<grid_c, 256, SMEM_GEMM>>>(hh, hl, wqh, wql, bq, nullptr, nullptr, qbh, qbl, Cc, Cc, 0.125f);
    tcgemm<3><<<grid_c, 256, SMEM_GEMM>>>(hh, hl, wkh, wkl, bk, nullptr, nullptr, kbh, kbl, Cc, Cc, 1.0f);
    tcgemm<3><<<grid_c, 256, SMEM_GEMM>>>(hh, hl, wvh, wvl, bv, nullptr, nullptr, vbh, vbl, Cc, Cc, 1.0f);
    // 3. attention -> ctx bf16 hi/lo
    attn_mma<<<dim3(Tt/128, Hh, Bb), 256, SMEM_ATTN>>>(qbh, qbl, kbh, kbl, vbh, vbl, ch, cl);
    // 4. x2 = x + ctx@Wo + bo
    tcgemm<2><<<grid_c, 256, SMEM_GEMM>>>(ch, cl, woh, wol, bo, x, x2, nullptr, nullptr, Cc, Cc, 1.0f);
    // 5. h2 = LN2(x2)
    ln_bf16_kernel<<<MM, 256>>>(x2, ln2s, ln2b, h2h, h2l);
    // 6. g = gelu(h2@W1 + b1) -> bf16 hi/lo
    tcgemm<1><<<grid_f, 256, SMEM_GEMM>>>(h2h, h2l, w1h, w1l, b1, nullptr, nullptr, gh, gl, Cc, Ff, 1.0f);
    // 7. out = x2 + g@W2 + b2
    tcgemm<2><<<grid_c, 256, SMEM_GEMM>>>(gh, gl, w2h, w2l, b2, x2, out, nullptr, nullptr, Ff, Cc, 1.0f);
}